// round 16
// baseline (speedup 1.0000x reference)
#include <cuda_runtime.h>
#include <cuda_fp16.h>
#include <math.h>
#include <stdint.h>

// ---------------- problem constants ----------------
#define S_LEN   2048
#define D_MODEL 1024
#define H_HEADS 32
#define P_DIM   64
#define N_STATE 64
#define G_GRP   8
#define K_CONV  4
#define D_INNER 2048                 // H*P
#define CONV_DIM 3072                // D_INNER + 2*G*N
#define D_PROJ  5152                 // 2*D_INNER + 2*G*N + H
#define GROUP_SIZE 256               // D_INNER / G
#define EPS_RMS 1e-5f

// proj row offsets
#define OFF_Z    0
#define OFF_XBC  2048
#define OFF_DT   5120
// xbc row offsets
#define OFF_XS   0
#define OFF_B    2048
#define OFF_C    2560

// ---------------- scratch (device globals; no allocation allowed) ----------------
__device__ __align__(16) __half g_xnh [S_LEN * D_MODEL];     // normed input, fp16
__device__ __align__(16) __half g_gh  [S_LEN * D_INNER];     // gated output, fp16
__device__ __align__(16) __half g_w1h [D_MODEL * D_PROJ];    // in_proj_w fp16
__device__ __align__(16) __half g_w2h [D_INNER * D_MODEL];   // out_proj_w fp16
__device__ __align__(16) float  g_proj[S_LEN * D_PROJ];      // also reused: out_proj partials
__device__ __align__(16) float  g_xbc [S_LEN * CONV_DIM];
__device__ __align__(16) float  g_dt  [S_LEN * H_HEADS];
__device__ __align__(16) float  g_dA  [S_LEN * H_HEADS];
__device__ __align__(16) float  g_y   [S_LEN * D_INNER];

__device__ __forceinline__ float sigmoidf_(float x) { return 1.0f / (1.0f + expf(-x)); }
__device__ __forceinline__ float siluf_(float x)    { return x * sigmoidf_(x); }

// pack two floats into f16x2 (lo in low half, hi in high half)
__device__ __forceinline__ uint32_t pack_half2(float lo, float hi) {
    uint32_t u;
    asm("cvt.rn.f16x2.f32 %0, %1, %2;" : "=r"(u) : "f"(hi), "f"(lo));
    return u;
}

// fp16 MMA m16n8k16, fp32 accumulate
__device__ __forceinline__ void mma_f16(float* c, const uint32_t* a,
                                        uint32_t b0, uint32_t b1) {
    asm("mma.sync.aligned.m16n8k16.row.col.f32.f16.f16.f32 "
        "{%0,%1,%2,%3}, {%4,%5,%6,%7}, {%8,%9}, {%0,%1,%2,%3};"
        : "+f"(c[0]), "+f"(c[1]), "+f"(c[2]), "+f"(c[3])
        : "r"(a[0]), "r"(a[1]), "r"(a[2]), "r"(a[3]), "r"(b0), "r"(b1));
}

#define LDSM_X4(r0, r1, r2, r3, addr) \
    asm volatile("ldmatrix.sync.aligned.m8n8.x4.shared.b16 {%0,%1,%2,%3}, [%4];" \
                 : "=r"(r0), "=r"(r1), "=r"(r2), "=r"(r3) : "r"(addr))
#define LDSM_X4_T(r0, r1, r2, r3, addr) \
    asm volatile("ldmatrix.sync.aligned.m8n8.x4.trans.shared.b16 {%0,%1,%2,%3}, [%4];" \
                 : "=r"(r0), "=r"(r1), "=r"(r2), "=r"(r3) : "r"(addr))

__device__ __forceinline__ uint32_t smem_u32(const void* p) {
    return (uint32_t)__cvta_generic_to_shared(p);
}

__device__ __forceinline__ void cp16(uint32_t dst, const void* src, int sz) {
    asm volatile("cp.async.cg.shared.global [%0], [%1], 16, %2;"
                 :: "r"(dst), "l"(src), "r"(sz));
}
__device__ __forceinline__ void cp16f(uint32_t dst, const void* src) {
    asm volatile("cp.async.cg.shared.global [%0], [%1], 16;"
                 :: "r"(dst), "l"(src));
}
#define CP_COMMIT() asm volatile("cp.async.commit_group;" ::: "memory")
#define CP_WAIT(n)  asm volatile("cp.async.wait_group %0;" :: "n"(n) : "memory")

// ---------------- 0. fused fp32 -> fp16 conversion (both weights) -------------
__global__ void f32h2_kernel(const float* __restrict__ s1, __half* __restrict__ d1, int n1,
                             const float* __restrict__ s2, __half* __restrict__ d2, int n2)
{
    int i = blockIdx.x * 256 + threadIdx.x;
    const float* s; __half* d; int j;
    if (i < n1) { s = s1; d = d1; j = i; }
    else        { j = i - n1; if (j >= n2) return; s = s2; d = d2; }
    float4 v = reinterpret_cast<const float4*>(s)[j];
    uint2 u;
    u.x = pack_half2(v.x, v.y);
    u.y = pack_half2(v.z, v.w);
    reinterpret_cast<uint2*>(d)[j] = u;
}

// ---------------- 1. RMSNorm (fp16 out) ----------------
__global__ void rmsnorm_kernel(const float* __restrict__ x,
                               const float* __restrict__ w)
{
    int s = blockIdx.x;
    int tid = threadIdx.x;                   // 256
    const float* row = x + (size_t)s * D_MODEL;
    float v[4];
    float ss = 0.f;
#pragma unroll
    for (int i = 0; i < 4; i++) {
        v[i] = row[tid + i * 256];
        ss += v[i] * v[i];
    }
    __shared__ float red[8];
#pragma unroll
    for (int o = 16; o > 0; o >>= 1) ss += __shfl_xor_sync(0xffffffffu, ss, o);
    if ((tid & 31) == 0) red[tid >> 5] = ss;
    __syncthreads();
    __shared__ float rinv;
    if (tid == 0) {
        float t = 0.f;
#pragma unroll
        for (int i = 0; i < 8; i++) t += red[i];
        rinv = rsqrtf(t / (float)D_MODEL + EPS_RMS);
    }
    __syncthreads();
    float r = rinv;
    __half* o = g_xnh + (size_t)s * D_MODEL;
#pragma unroll
    for (int i = 0; i < 4; i++) {
        int c = tid + i * 256;
        o[c] = __float2half(v[i] * r * w[c]);
    }
}

// ---------------- 2. fp16 GEMM, 4-stage cp.async, 1 barrier/stage -------------
// C[z*M + M,N] += A[M, kOff..kOff+K] @ B[kOff.., N], kOff = blockIdx.z * K.
#define GBM 128
#define GBK 32
#define AROW 80
#define ASTG (GBM * AROW)
#define NSTAGE 4

template<int BN>
__global__ __launch_bounds__(256, 2)
void gemm_h_kernel(const __half* __restrict__ A,
                   const __half* __restrict__ B,
                   const float* __restrict__ resid,  // may be null
                   float* __restrict__ C,
                   int M, int N, int K, int lda)
{
    constexpr int BROW = BN * 2 + 16;
    constexpr int BSTG = GBK * BROW;
    constexpr int NT   = BN / 16;
    constexpr int NBC  = (GBK * (BN / 8)) / 256;

    extern __shared__ __align__(16) uint8_t smem[];
    uint32_t saA = smem_u32(smem);
    uint32_t saB = saA + NSTAGE * ASTG;

    int tid = threadIdx.x;
    int wid = tid >> 5, lane = tid & 31;
    int warpM = wid & 3;
    int warpN = wid >> 2;
    int grp = lane >> 2, tig = lane & 3;

    int rowBase = blockIdx.y * GBM;
    int colBase = blockIdx.x * BN;
    int kOff    = blockIdx.z * K;
    size_t cOff = (size_t)blockIdx.z * M * N;

    float acc[2][NT][4];
#pragma unroll
    for (int mt = 0; mt < 2; mt++)
#pragma unroll
        for (int nt = 0; nt < NT; nt++)
#pragma unroll
            for (int r = 0; r < 4; r++) acc[mt][nt][r] = 0.f;

    int KT = K / GBK;

    auto issue_stage = [&](int kt) {
        int buf = kt % NSTAGE;
        int k0 = kOff + kt * GBK;
#pragma unroll
        for (int i = 0; i < 2; i++) {
            int idx = tid + i * 256;
            int r  = idx >> 2;
            int kq = idx & 3;
            cp16f(saA + buf * ASTG + r * AROW + kq * 16,
                  A + (size_t)(rowBase + r) * lda + k0 + kq * 8);
        }
#pragma unroll
        for (int i = 0; i < NBC; i++) {
            int idx = tid + i * 256;
            int kk = idx / (BN / 8);
            int cq = idx % (BN / 8);
            int gc = colBase + cq * 8;
            int ok = (gc < N);
            cp16(saB + buf * BSTG + kk * BROW + cq * 16,
                 B + (size_t)(k0 + kk) * N + (ok ? gc : 0), ok ? 16 : 0);
        }
        CP_COMMIT();
    };

    int a_lr = lane & 15;
    int a_lc = lane >> 4;
    int b_kof = (lane & 7) + ((lane >> 4) << 3);
    int b_nch = ((lane >> 3) & 1) * 8;

    issue_stage(0);
    issue_stage(1);
    issue_stage(2);

    for (int kt = 0; kt < KT; kt++) {
        CP_WAIT(2);
        __syncthreads();
        if (kt + 3 < KT) issue_stage(kt + 3);
        else             CP_COMMIT();

        int buf = kt % NSTAGE;
        uint32_t sa_base = saA + buf * ASTG;
        uint32_t sb_base = saB + buf * BSTG;
#pragma unroll
        for (int kk = 0; kk < 2; kk++) {
            uint32_t a[2][4];
#pragma unroll
            for (int mt = 0; mt < 2; mt++) {
                int m0 = warpM * 32 + mt * 16;
                uint32_t addr = sa_base + (m0 + a_lr) * AROW + kk * 32 + a_lc * 16;
                LDSM_X4(a[mt][0], a[mt][1], a[mt][2], a[mt][3], addr);
            }
#pragma unroll
            for (int j = 0; j < NT / 2; j++) {
                int n0 = warpN * (BN / 2) + j * 16;
                uint32_t addr = sb_base + (kk * 16 + b_kof) * BROW + (n0 + b_nch) * 2;
                uint32_t b0a, b0b, b1a, b1b;
                LDSM_X4_T(b0a, b0b, b1a, b1b, addr);
                mma_f16(acc[0][2 * j    ], a[0], b0a, b1a);
                mma_f16(acc[1][2 * j    ], a[1], b0a, b1a);
                mma_f16(acc[0][2 * j + 1], a[0], b0b, b1b);
                mma_f16(acc[1][2 * j + 1], a[1], b0b, b1b);
            }
        }
    }

    // ---- epilogue ----
#pragma unroll
    for (int mt = 0; mt < 2; mt++) {
        int row0 = rowBase + warpM * 32 + mt * 16 + grp;
#pragma unroll
        for (int nt = 0; nt < NT; nt++) {
            int col0 = colBase + warpN * (BN / 2) + nt * 8 + tig * 2;
#pragma unroll
            for (int rr = 0; rr < 2; rr++) {
                int gr = row0 + rr * 8;
#pragma unroll
                for (int cc = 0; cc < 2; cc++) {
                    int gc = col0 + cc;
                    if (gc < N) {
                        float v = acc[mt][nt][rr * 2 + cc];
                        if (resid) v += resid[(size_t)gr * N + gc];
                        C[cOff + (size_t)gr * N + gc] = v;
                    }
                }
            }
        }
    }
}

#define GEMM_SMEM_BN(BN) (NSTAGE * ASTG + NSTAGE * GBK * ((BN) * 2 + 16))

// ---------------- 2b. split-K combine: out = p0 + p1 + residual ---------------
__global__ void addk_kernel(const float* __restrict__ p0,
                            const float* __restrict__ p1,
                            const float* __restrict__ resid,
                            float* __restrict__ out)
{
    size_t i = (size_t)blockIdx.x * 256 + threadIdx.x;   // float4 index
    float4 a = reinterpret_cast<const float4*>(p0)[i];
    float4 b = reinterpret_cast<const float4*>(p1)[i];
    float4 r = reinterpret_cast<const float4*>(resid)[i];
    float4 o;
    o.x = a.x + b.x + r.x;
    o.y = a.y + b.y + r.y;
    o.z = a.z + b.z + r.z;
    o.w = a.w + b.w + r.w;
    reinterpret_cast<float4*>(out)[i] = o;
}

// ---------------- 3. conv v2 (4 s/thread, window in regs) + dt fused ----------
// fp32 output (R13 form). grid (13, 512), block 256.
__global__ void conv_dt_kernel(const float* __restrict__ cw,
                               const float* __restrict__ cb,
                               const float* __restrict__ dt_bias,
                               const float* __restrict__ A_log)
{
    int tid = threadIdx.x;
    int s0 = blockIdx.y * 4;

    if (blockIdx.x == 12) {
        if (tid < 128) {
            int e = blockIdx.y * 128 + tid;
            int s = e >> 5;
            int h = e & 31;
            float x = g_proj[(size_t)s * D_PROJ + OFF_DT + h] + dt_bias[h];
            float dt = (x > 20.f) ? x : log1pf(expf(x));
            float A = -expf(A_log[h]);
            g_dt[e] = dt;
            g_dA[e] = expf(dt * A);
        }
        return;
    }

    int c = blockIdx.x * 256 + tid;
    float k0 = cw[c * K_CONV + 0];
    float k1 = cw[c * K_CONV + 1];
    float k2 = cw[c * K_CONV + 2];
    float k3 = cw[c * K_CONV + 3];
    float bias = cb[c];

    const float* src = g_proj + (size_t)s0 * D_PROJ + OFF_XBC + c;
    float* dst = g_xbc + (size_t)s0 * CONV_DIM + c;

    float w0 = (s0 >= 3) ? src[-(ptrdiff_t)3 * D_PROJ] : 0.f;
    float w1 = (s0 >= 2) ? src[-(ptrdiff_t)2 * D_PROJ] : 0.f;
    float w2 = (s0 >= 1) ? src[-(ptrdiff_t)1 * D_PROJ] : 0.f;

#pragma unroll
    for (int i = 0; i < 4; i++) {
        float cur = src[(size_t)i * D_PROJ];
        float acc = bias + k0 * w0 + k1 * w1 + k2 * w2 + k3 * cur;
        dst[(size_t)i * CONV_DIM] = siluf_(acc);
        w0 = w1; w1 = w2; w2 = cur;
    }
}

// ---------------- 5. SSM scan v5: q=4, 8 states/thread, 128 thr ---------------
// grid (H, 4), block 128. Block handles p in [q*16, q*16+16).
// Thread = (p_local = tid&15, seg = tid>>4); owns n in [seg*8, seg*8+8).
// Partial y -> flat sy[t*165 + p*10 + seg] (write banks 10p+s distinct/warp;
// reduce banks 5tt+10pp distinct/warp). Per-chunk reduce sums 8 partials.
#define CHUNK 16
#define SY_T 165
#define SY_P 10
__global__ void scan_kernel()
{
    int h  = blockIdx.x;
    int q  = blockIdx.y;                  // 0..3
    int g  = h >> 2;
    int pbase = q * 16;

    int tid = threadIdx.x;                // 0..127
    int p_local = tid & 15;               // 0..15
    int seg = tid >> 4;                   // 0..7
    int nbase = seg * 8;

    __shared__ __align__(16) float sx[CHUNK][16];
    __shared__ __align__(16) float sB[CHUNK][64];
    __shared__ __align__(16) float sC[CHUNK][64];
    __shared__ float sdA[CHUNK];
    __shared__ float sdt[CHUNK];
    __shared__ float sy[CHUNK * SY_T];

    float hs[8];
#pragma unroll
    for (int i = 0; i < 8; i++) hs[i] = 0.f;

    for (int s0 = 0; s0 < S_LEN; s0 += CHUNK) {
#pragma unroll
        for (int i = 0; i < 2; i++) {   // x: 16x16
            int t  = tid + i * 128;
            int tt = t >> 4;
            int cc = t & 15;
            sx[tt][cc] = g_xbc[(size_t)(s0 + tt) * CONV_DIM + OFF_XS + h * 64 + pbase + cc];
        }
#pragma unroll
        for (int i = 0; i < 8; i++) {   // B, C: 16x64 each
            int t  = tid + i * 128;
            int tt = t >> 6;
            int cc = t & 63;
            size_t base = (size_t)(s0 + tt) * CONV_DIM;
            sB[tt][cc] = g_xbc[base + OFF_B + g * 64 + cc];
            sC[tt][cc] = g_xbc[base + OFF_C + g * 64 + cc];
        }
        if (tid < CHUNK) {
            sdA[tid] = g_dA[(size_t)(s0 + tid) * H_HEADS + h];
            sdt[tid] = g_dt[(size_t)(s0 + tid) * H_HEADS + h];
        }
        __syncthreads();

#pragma unroll 4
        for (int t = 0; t < CHUNK; t++) {
            float dAv  = sdA[t];
            float coef = sdt[t] * sx[t][p_local];
            float4 b0 = *reinterpret_cast<const float4*>(&sB[t][nbase]);
            float4 b1 = *reinterpret_cast<const float4*>(&sB[t][nbase + 4]);
            float4 c0 = *reinterpret_cast<const float4*>(&sC[t][nbase]);
            float4 c1 = *reinterpret_cast<const float4*>(&sC[t][nbase + 4]);
            float ya, yb;
            hs[0] = dAv * hs[0] + coef * b0.x;  ya  = hs[0] * c0.x;
            hs[1] = dAv * hs[1] + coef * b0.y;  yb  = hs[1] * c0.y;
            hs[2] = dAv * hs[2] + coef * b0.z;  ya += hs[2] * c0.z;
            hs[3] = dAv * hs[3] + coef * b0.w;  yb += hs[3] * c0.w;
            hs[4] = dAv * hs[4] + coef * b1.x;  ya += hs[4] * c1.x;
            hs[5] = dAv * hs[5] + coef * b1.y;  yb += hs[5] * c1.y;
            hs[6] = dAv * hs[6] + coef * b1.z;  ya += hs[6] * c1.z;
            hs[7] = dAv * hs[7] + coef * b1.w;  yb += hs[7] * c1.w;
            sy[t * SY_T + p_local * SY_P + seg] = ya + yb;
        }
        __syncthreads();

#pragma unroll
        for (int i = 0; i < 2; i++) {   // reduce 256 (t,p) pairs, 2 per thread
            int e  = tid + i * 128;
            int tt = e >> 4;
            int pp = e & 15;
            const float* row = &sy[tt * SY_T + pp * SY_P];
            float acc = 0.f;
#pragma unroll
            for (int j = 0; j < 8; j++) acc += row[j];
            g_y[(size_t)(s0 + tt) * D_INNER + h * 64 + pbase + pp] = acc;
        }
        __syncthreads();
    }
}

// ---------------- 6. gating + grouped RMSNorm (fp16 out) ----------------
__global__ void gate_kernel(const float* __restrict__ Dv,
                            const float* __restrict__ gw)
{
    int s = blockIdx.y;
    int grp = blockIdx.x;
    int tid = threadIdx.x;
    int d = grp * GROUP_SIZE + tid;
    int h = d >> 6;

    float xs = g_xbc[(size_t)s * CONV_DIM + OFF_XS + d];
    float y  = g_y[(size_t)s * D_INNER + d] + Dv[h] * xs;
    float z  = g_proj[(size_t)s * D_PROJ + OFF_Z + d];
    float gv = y * siluf_(z);

    float ss = gv * gv;
    __shared__ float red[8];
#pragma unroll
    for (int o = 16; o > 0; o >>= 1) ss += __shfl_xor_sync(0xffffffffu, ss, o);
    if ((tid & 31) == 0) red[tid >> 5] = ss;
    __syncthreads();
    __shared__ float rinv;
    if (tid == 0) {
        float t = 0.f;
#pragma unroll
        for (int i = 0; i < 8; i++) t += red[i];
        rinv = rsqrtf(t / (float)GROUP_SIZE + EPS_RMS);
    }
    __syncthreads();
    g_gh[(size_t)s * D_INNER + d] = __float2half(gv * rinv * gw[d]);
}

// ---------------- launch ----------------
extern "C" void kernel_launch(void* const* d_in, const int* in_sizes, int n_in,
                              void* d_out, int out_size)
{
    const float* hidden      = (const float*)d_in[0];
    const float* norm_w      = (const float*)d_in[1];
    const float* in_proj_w   = (const float*)d_in[2];
    const float* conv_w      = (const float*)d_in[3];
    const float* conv_b      = (const float*)d_in[4];
    const float* dt_bias     = (const float*)d_in[5];
    const float* A_log       = (const float*)d_in[6];
    const float* Dv          = (const float*)d_in[7];
    const float* gate_norm_w = (const float*)d_in[8];
    const float* out_proj_w  = (const float*)d_in[9];
    float* out = (float*)d_out;

    void *p_xnh, *p_proj, *p_gh, *p_w1h, *p_w2h;
    cudaGetSymbolAddress(&p_xnh,  g_xnh);
    cudaGetSymbolAddress(&p_proj, g_proj);
    cudaGetSymbolAddress(&p_gh,   g_gh);
    cudaGetSymbolAddress(&p_w1h,  g_w1h);
    cudaGetSymbolAddress(&p_w2h,  g_w2h);

    cudaFuncSetAttribute(gemm_h_kernel<128>,
                         cudaFuncAttributeMaxDynamicSharedMemorySize,
                         GEMM_SMEM_BN(128));

    // fused weight conversion prepass (fp32 -> fp16)
    {
        int n1 = (D_MODEL * D_PROJ) / 4;
        int n2 = (D_INNER * D_MODEL) / 4;
        f32h2_kernel<<<(n1 + n2 + 255) / 256, 256>>>(
            in_proj_w, (__half*)p_w1h, n1, out_proj_w, (__half*)p_w2h, n2);
    }

    rmsnorm_kernel<<<S_LEN, 256>>>(hidden, norm_w);

    // in_proj: C = xn @ W1   [2048 x 5152]
    gemm_h_kernel<128><<<dim3((D_PROJ + 127) / 128, S_LEN / GBM, 1), 256,
                         GEMM_SMEM_BN(128)>>>(
        (const __half*)p_xnh, (const __half*)p_w1h, nullptr, (float*)p_proj,
        S_LEN, D_PROJ, D_MODEL, D_MODEL);

    conv_dt_kernel<<<dim3(13, S_LEN / 4), 256>>>(conv_w, conv_b, dt_bias, A_log);

    scan_kernel<<<dim3(H_HEADS, 4), 128>>>();

    gate_kernel<<<dim3(G_GRP, S_LEN), 256>>>(Dv, gate_norm_w);

    // out_proj split-K=2: partials into g_proj (dead after gate)
    float* part = (float*)p_proj;   // p0 = part, p1 = part + S_LEN*D_MODEL
    gemm_h_kernel<128><<<dim3(D_MODEL / 128, S_LEN / GBM, 2), 256,
                         GEMM_SMEM_BN(128)>>>(
        (const __half*)p_gh, (const __half*)p_w2h, nullptr, part,
        S_LEN, D_MODEL, D_INNER / 2, D_INNER);

    addk_kernel<<<(S_LEN * D_MODEL / 4) / 256, 256>>>(
        part, part + (size_t)S_LEN * D_MODEL, hidden, out);
}

// round 17
// speedup vs baseline: 1.2267x; 1.2267x over previous
#include <cuda_runtime.h>
#include <cuda_fp16.h>
#include <math.h>
#include <stdint.h>

// ---------------- problem constants ----------------
#define S_LEN   2048
#define D_MODEL 1024
#define H_HEADS 32
#define P_DIM   64
#define N_STATE 64
#define G_GRP   8
#define K_CONV  4
#define D_INNER 2048                 // H*P
#define CONV_DIM 3072                // D_INNER + 2*G*N
#define D_PROJ  5152                 // 2*D_INNER + 2*G*N + H
#define GROUP_SIZE 256               // D_INNER / G
#define EPS_RMS 1e-5f

// proj row offsets
#define OFF_Z    0
#define OFF_XBC  2048
#define OFF_DT   5120
// xbc row offsets
#define OFF_XS   0
#define OFF_B    2048
#define OFF_C    2560

// ---------------- scratch (device globals; no allocation allowed) ----------------
__device__ __align__(16) __half g_xnh [S_LEN * D_MODEL];     // normed input, fp16
__device__ __align__(16) __half g_gh  [S_LEN * D_INNER];     // gated output, fp16
__device__ __align__(16) __half g_w1h [D_MODEL * D_PROJ];    // in_proj_w fp16
__device__ __align__(16) __half g_w2h [D_INNER * D_MODEL];   // out_proj_w fp16
__device__ __align__(16) float  g_proj[S_LEN * D_PROJ];      // also reused: out_proj partials
__device__ __align__(16) float  g_xbc [S_LEN * CONV_DIM];
__device__ __align__(16) float  g_dt  [S_LEN * H_HEADS];
__device__ __align__(16) float  g_dA  [S_LEN * H_HEADS];
__device__ __align__(16) float  g_y   [S_LEN * D_INNER];

__device__ __forceinline__ float sigmoidf_(float x) { return 1.0f / (1.0f + expf(-x)); }
__device__ __forceinline__ float siluf_(float x)    { return x * sigmoidf_(x); }

// pack two floats into f16x2 (lo in low half, hi in high half)
__device__ __forceinline__ uint32_t pack_half2(float lo, float hi) {
    uint32_t u;
    asm("cvt.rn.f16x2.f32 %0, %1, %2;" : "=r"(u) : "f"(hi), "f"(lo));
    return u;
}

// fp16 MMA m16n8k16, fp32 accumulate
__device__ __forceinline__ void mma_f16(float* c, const uint32_t* a,
                                        uint32_t b0, uint32_t b1) {
    asm("mma.sync.aligned.m16n8k16.row.col.f32.f16.f16.f32 "
        "{%0,%1,%2,%3}, {%4,%5,%6,%7}, {%8,%9}, {%0,%1,%2,%3};"
        : "+f"(c[0]), "+f"(c[1]), "+f"(c[2]), "+f"(c[3])
        : "r"(a[0]), "r"(a[1]), "r"(a[2]), "r"(a[3]), "r"(b0), "r"(b1));
}

#define LDSM_X4(r0, r1, r2, r3, addr) \
    asm volatile("ldmatrix.sync.aligned.m8n8.x4.shared.b16 {%0,%1,%2,%3}, [%4];" \
                 : "=r"(r0), "=r"(r1), "=r"(r2), "=r"(r3) : "r"(addr))
#define LDSM_X4_T(r0, r1, r2, r3, addr) \
    asm volatile("ldmatrix.sync.aligned.m8n8.x4.trans.shared.b16 {%0,%1,%2,%3}, [%4];" \
                 : "=r"(r0), "=r"(r1), "=r"(r2), "=r"(r3) : "r"(addr))

__device__ __forceinline__ uint32_t smem_u32(const void* p) {
    return (uint32_t)__cvta_generic_to_shared(p);
}

__device__ __forceinline__ void cp16(uint32_t dst, const void* src, int sz) {
    asm volatile("cp.async.cg.shared.global [%0], [%1], 16, %2;"
                 :: "r"(dst), "l"(src), "r"(sz));
}
__device__ __forceinline__ void cp16f(uint32_t dst, const void* src) {
    asm volatile("cp.async.cg.shared.global [%0], [%1], 16;"
                 :: "r"(dst), "l"(src));
}
#define CP_COMMIT() asm volatile("cp.async.commit_group;" ::: "memory")
#define CP_WAIT(n)  asm volatile("cp.async.wait_group %0;" :: "n"(n) : "memory")

// ---------------- 0. fused fp32 -> fp16 conversion (both weights) -------------
__global__ void f32h2_kernel(const float* __restrict__ s1, __half* __restrict__ d1, int n1,
                             const float* __restrict__ s2, __half* __restrict__ d2, int n2)
{
    int i = blockIdx.x * 256 + threadIdx.x;
    const float* s; __half* d; int j;
    if (i < n1) { s = s1; d = d1; j = i; }
    else        { j = i - n1; if (j >= n2) return; s = s2; d = d2; }
    float4 v = reinterpret_cast<const float4*>(s)[j];
    uint2 u;
    u.x = pack_half2(v.x, v.y);
    u.y = pack_half2(v.z, v.w);
    reinterpret_cast<uint2*>(d)[j] = u;
}

// ---------------- 1. RMSNorm (fp16 out) ----------------
__global__ void rmsnorm_kernel(const float* __restrict__ x,
                               const float* __restrict__ w)
{
    int s = blockIdx.x;
    int tid = threadIdx.x;                   // 256
    const float* row = x + (size_t)s * D_MODEL;
    float v[4];
    float ss = 0.f;
#pragma unroll
    for (int i = 0; i < 4; i++) {
        v[i] = row[tid + i * 256];
        ss += v[i] * v[i];
    }
    __shared__ float red[8];
#pragma unroll
    for (int o = 16; o > 0; o >>= 1) ss += __shfl_xor_sync(0xffffffffu, ss, o);
    if ((tid & 31) == 0) red[tid >> 5] = ss;
    __syncthreads();
    __shared__ float rinv;
    if (tid == 0) {
        float t = 0.f;
#pragma unroll
        for (int i = 0; i < 8; i++) t += red[i];
        rinv = rsqrtf(t / (float)D_MODEL + EPS_RMS);
    }
    __syncthreads();
    float r = rinv;
    __half* o = g_xnh + (size_t)s * D_MODEL;
#pragma unroll
    for (int i = 0; i < 4; i++) {
        int c = tid + i * 256;
        o[c] = __float2half(v[i] * r * w[c]);
    }
}

// ---------------- 2. fp16 GEMM, 4-stage cp.async, 1 barrier/stage -------------
// C[z*M + M,N] += A[M, kOff..kOff+K] @ B[kOff.., N], kOff = blockIdx.z * K.
#define GBM 128
#define GBK 32
#define AROW 80
#define ASTG (GBM * AROW)
#define NSTAGE 4

template<int BN>
__global__ __launch_bounds__(256, 2)
void gemm_h_kernel(const __half* __restrict__ A,
                   const __half* __restrict__ B,
                   const float* __restrict__ resid,  // may be null
                   float* __restrict__ C,
                   int M, int N, int K, int lda)
{
    constexpr int BROW = BN * 2 + 16;
    constexpr int BSTG = GBK * BROW;
    constexpr int NT   = BN / 16;
    constexpr int NBC  = (GBK * (BN / 8)) / 256;

    extern __shared__ __align__(16) uint8_t smem[];
    uint32_t saA = smem_u32(smem);
    uint32_t saB = saA + NSTAGE * ASTG;

    int tid = threadIdx.x;
    int wid = tid >> 5, lane = tid & 31;
    int warpM = wid & 3;
    int warpN = wid >> 2;
    int grp = lane >> 2, tig = lane & 3;

    int rowBase = blockIdx.y * GBM;
    int colBase = blockIdx.x * BN;
    int kOff    = blockIdx.z * K;
    size_t cOff = (size_t)blockIdx.z * M * N;

    float acc[2][NT][4];
#pragma unroll
    for (int mt = 0; mt < 2; mt++)
#pragma unroll
        for (int nt = 0; nt < NT; nt++)
#pragma unroll
            for (int r = 0; r < 4; r++) acc[mt][nt][r] = 0.f;

    int KT = K / GBK;

    auto issue_stage = [&](int kt) {
        int buf = kt % NSTAGE;
        int k0 = kOff + kt * GBK;
#pragma unroll
        for (int i = 0; i < 2; i++) {
            int idx = tid + i * 256;
            int r  = idx >> 2;
            int kq = idx & 3;
            cp16f(saA + buf * ASTG + r * AROW + kq * 16,
                  A + (size_t)(rowBase + r) * lda + k0 + kq * 8);
        }
#pragma unroll
        for (int i = 0; i < NBC; i++) {
            int idx = tid + i * 256;
            int kk = idx / (BN / 8);
            int cq = idx % (BN / 8);
            int gc = colBase + cq * 8;
            int ok = (gc < N);
            cp16(saB + buf * BSTG + kk * BROW + cq * 16,
                 B + (size_t)(k0 + kk) * N + (ok ? gc : 0), ok ? 16 : 0);
        }
        CP_COMMIT();
    };

    int a_lr = lane & 15;
    int a_lc = lane >> 4;
    int b_kof = (lane & 7) + ((lane >> 4) << 3);
    int b_nch = ((lane >> 3) & 1) * 8;

    issue_stage(0);
    issue_stage(1);
    issue_stage(2);

    for (int kt = 0; kt < KT; kt++) {
        CP_WAIT(2);
        __syncthreads();
        if (kt + 3 < KT) issue_stage(kt + 3);
        else             CP_COMMIT();

        int buf = kt % NSTAGE;
        uint32_t sa_base = saA + buf * ASTG;
        uint32_t sb_base = saB + buf * BSTG;
#pragma unroll
        for (int kk = 0; kk < 2; kk++) {
            uint32_t a[2][4];
#pragma unroll
            for (int mt = 0; mt < 2; mt++) {
                int m0 = warpM * 32 + mt * 16;
                uint32_t addr = sa_base + (m0 + a_lr) * AROW + kk * 32 + a_lc * 16;
                LDSM_X4(a[mt][0], a[mt][1], a[mt][2], a[mt][3], addr);
            }
#pragma unroll
            for (int j = 0; j < NT / 2; j++) {
                int n0 = warpN * (BN / 2) + j * 16;
                uint32_t addr = sb_base + (kk * 16 + b_kof) * BROW + (n0 + b_nch) * 2;
                uint32_t b0a, b0b, b1a, b1b;
                LDSM_X4_T(b0a, b0b, b1a, b1b, addr);
                mma_f16(acc[0][2 * j    ], a[0], b0a, b1a);
                mma_f16(acc[1][2 * j    ], a[1], b0a, b1a);
                mma_f16(acc[0][2 * j + 1], a[0], b0b, b1b);
                mma_f16(acc[1][2 * j + 1], a[1], b0b, b1b);
            }
        }
    }

    // ---- epilogue ----
#pragma unroll
    for (int mt = 0; mt < 2; mt++) {
        int row0 = rowBase + warpM * 32 + mt * 16 + grp;
#pragma unroll
        for (int nt = 0; nt < NT; nt++) {
            int col0 = colBase + warpN * (BN / 2) + nt * 8 + tig * 2;
#pragma unroll
            for (int rr = 0; rr < 2; rr++) {
                int gr = row0 + rr * 8;
#pragma unroll
                for (int cc = 0; cc < 2; cc++) {
                    int gc = col0 + cc;
                    if (gc < N) {
                        float v = acc[mt][nt][rr * 2 + cc];
                        if (resid) v += resid[(size_t)gr * N + gc];
                        C[cOff + (size_t)gr * N + gc] = v;
                    }
                }
            }
        }
    }
}

#define GEMM_SMEM_BN(BN) (NSTAGE * ASTG + NSTAGE * GBK * ((BN) * 2 + 16))

// ---------------- 2b. split-K combine: out = p0 + p1 + residual ---------------
__global__ void addk_kernel(const float* __restrict__ p0,
                            const float* __restrict__ p1,
                            const float* __restrict__ resid,
                            float* __restrict__ out)
{
    size_t i = (size_t)blockIdx.x * 256 + threadIdx.x;   // float4 index
    float4 a = reinterpret_cast<const float4*>(p0)[i];
    float4 b = reinterpret_cast<const float4*>(p1)[i];
    float4 r = reinterpret_cast<const float4*>(resid)[i];
    float4 o;
    o.x = a.x + b.x + r.x;
    o.y = a.y + b.y + r.y;
    o.z = a.z + b.z + r.z;
    o.w = a.w + b.w + r.w;
    reinterpret_cast<float4*>(out)[i] = o;
}

// ---------------- 3. conv v2 (4 s/thread, window in regs) + dt fused ----------
// grid (13, 512), block 256.
__global__ void conv_dt_kernel(const float* __restrict__ cw,
                               const float* __restrict__ cb,
                               const float* __restrict__ dt_bias,
                               const float* __restrict__ A_log)
{
    int tid = threadIdx.x;
    int s0 = blockIdx.y * 4;

    if (blockIdx.x == 12) {
        if (tid < 128) {
            int e = blockIdx.y * 128 + tid;
            int s = e >> 5;
            int h = e & 31;
            float x = g_proj[(size_t)s * D_PROJ + OFF_DT + h] + dt_bias[h];
            float dt = (x > 20.f) ? x : log1pf(expf(x));
            float A = -expf(A_log[h]);
            g_dt[e] = dt;
            g_dA[e] = expf(dt * A);
        }
        return;
    }

    int c = blockIdx.x * 256 + tid;
    float k0 = cw[c * K_CONV + 0];
    float k1 = cw[c * K_CONV + 1];
    float k2 = cw[c * K_CONV + 2];
    float k3 = cw[c * K_CONV + 3];
    float bias = cb[c];

    const float* src = g_proj + (size_t)s0 * D_PROJ + OFF_XBC + c;
    float* dst = g_xbc + (size_t)s0 * CONV_DIM + c;

    float w0 = (s0 >= 3) ? src[-(ptrdiff_t)3 * D_PROJ] : 0.f;
    float w1 = (s0 >= 2) ? src[-(ptrdiff_t)2 * D_PROJ] : 0.f;
    float w2 = (s0 >= 1) ? src[-(ptrdiff_t)1 * D_PROJ] : 0.f;

#pragma unroll
    for (int i = 0; i < 4; i++) {
        float cur = src[(size_t)i * D_PROJ];
        float acc = bias + k0 * w0 + k1 * w1 + k2 * w2 + k3 * cur;
        dst[(size_t)i * CONV_DIM] = siluf_(acc);
        w0 = w1; w1 = w2; w2 = cur;
    }
}

// ---------------- 5. SSM scan v3 (R13 form): p-split x8, 128 thr --------------
// grid (H, 8), block 128. Block handles p in [q*8, q*8+8).
// Thread layout: p_local = w*2 + (lane&1) (w = warp 0..3),
//                seg = lane>>1 (0..15), n = seg*4..+4 (4 state regs).
#define CHUNK 16
__global__ void scan_kernel()
{
    int h  = blockIdx.x;
    int q  = blockIdx.y;                  // 0..7
    int g  = h >> 2;
    int pbase = q * 8;

    int tid = threadIdx.x;                // 0..127
    int w = tid >> 5;
    int lane = tid & 31;
    int p_local = w * 2 + (lane & 1);     // 0..7
    int seg = lane >> 1;                  // 0..15
    int nbase = seg * 4;

    __shared__ __align__(16) float sx[CHUNK][8];
    __shared__ __align__(16) float sB[CHUNK][64];
    __shared__ __align__(16) float sC[CHUNK][64];
    __shared__ float sdA[CHUNK];
    __shared__ float sdt[CHUNK];
    __shared__ float sy[CHUNK][8][17];

    float hs[4];
#pragma unroll
    for (int i = 0; i < 4; i++) hs[i] = 0.f;

    for (int s0 = 0; s0 < S_LEN; s0 += CHUNK) {
        {   // x: 16x8 = 128 elements, one per thread
            int tt = tid >> 3;
            int cc = tid & 7;
            sx[tt][cc] = g_xbc[(size_t)(s0 + tt) * CONV_DIM + OFF_XS + h * 64 + pbase + cc];
        }
#pragma unroll
        for (int i = 0; i < 8; i++) {   // B, C: 16x64 each
            int t  = tid + i * 128;
            int tt = t >> 6;
            int cc = t & 63;
            size_t base = (size_t)(s0 + tt) * CONV_DIM;
            sB[tt][cc] = g_xbc[base + OFF_B + g * 64 + cc];
            sC[tt][cc] = g_xbc[base + OFF_C + g * 64 + cc];
        }
        if (tid < CHUNK) {
            sdA[tid] = g_dA[(size_t)(s0 + tid) * H_HEADS + h];
            sdt[tid] = g_dt[(size_t)(s0 + tid) * H_HEADS + h];
        }
        __syncthreads();

#pragma unroll 4
        for (int t = 0; t < CHUNK; t++) {
            float dAv  = sdA[t];
            float coef = sdt[t] * sx[t][p_local];
            float4 b = *reinterpret_cast<const float4*>(&sB[t][nbase]);
            float4 c = *reinterpret_cast<const float4*>(&sC[t][nbase]);
            hs[0] = dAv * hs[0] + coef * b.x;
            hs[1] = dAv * hs[1] + coef * b.y;
            hs[2] = dAv * hs[2] + coef * b.z;
            hs[3] = dAv * hs[3] + coef * b.w;
            float y01 = hs[0] * c.x + hs[1] * c.y;
            float y23 = hs[2] * c.z + hs[3] * c.w;
            sy[t][p_local][seg] = y01 + y23;   // no shfl chain
        }
        __syncthreads();

        {   // reduce 16 partials per (t,p); 128 pairs, one per thread
            int tt = tid >> 3;
            int pp = tid & 7;
            const float* row = sy[tt][pp];
            float acc = 0.f;
#pragma unroll
            for (int i = 0; i < 16; i++) acc += row[i];
            g_y[(size_t)(s0 + tt) * D_INNER + h * 64 + pbase + pp] = acc;
        }
        __syncthreads();
    }
}

// ---------------- 6. gating + grouped RMSNorm (fp16 out) ----------------
__global__ void gate_kernel(const float* __restrict__ Dv,
                            const float* __restrict__ gw)
{
    int s = blockIdx.y;
    int grp = blockIdx.x;
    int tid = threadIdx.x;
    int d = grp * GROUP_SIZE + tid;
    int h = d >> 6;

    float xs = g_xbc[(size_t)s * CONV_DIM + OFF_XS + d];
    float y  = g_y[(size_t)s * D_INNER + d] + Dv[h] * xs;
    float z  = g_proj[(size_t)s * D_PROJ + OFF_Z + d];
    float gv = y * siluf_(z);

    float ss = gv * gv;
    __shared__ float red[8];
#pragma unroll
    for (int o = 16; o > 0; o >>= 1) ss += __shfl_xor_sync(0xffffffffu, ss, o);
    if ((tid & 31) == 0) red[tid >> 5] = ss;
    __syncthreads();
    __shared__ float rinv;
    if (tid == 0) {
        float t = 0.f;
#pragma unroll
        for (int i = 0; i < 8; i++) t += red[i];
        rinv = rsqrtf(t / (float)GROUP_SIZE + EPS_RMS);
    }
    __syncthreads();
    g_gh[(size_t)s * D_INNER + d] = __float2half(gv * rinv * gw[d]);
}

// ---------------- launch ----------------
extern "C" void kernel_launch(void* const* d_in, const int* in_sizes, int n_in,
                              void* d_out, int out_size)
{
    const float* hidden      = (const float*)d_in[0];
    const float* norm_w      = (const float*)d_in[1];
    const float* in_proj_w   = (const float*)d_in[2];
    const float* conv_w      = (const float*)d_in[3];
    const float* conv_b      = (const float*)d_in[4];
    const float* dt_bias     = (const float*)d_in[5];
    const float* A_log       = (const float*)d_in[6];
    const float* Dv          = (const float*)d_in[7];
    const float* gate_norm_w = (const float*)d_in[8];
    const float* out_proj_w  = (const float*)d_in[9];
    float* out = (float*)d_out;

    void *p_xnh, *p_proj, *p_gh, *p_w1h, *p_w2h;
    cudaGetSymbolAddress(&p_xnh,  g_xnh);
    cudaGetSymbolAddress(&p_proj, g_proj);
    cudaGetSymbolAddress(&p_gh,   g_gh);
    cudaGetSymbolAddress(&p_w1h,  g_w1h);
    cudaGetSymbolAddress(&p_w2h,  g_w2h);

    cudaFuncSetAttribute(gemm_h_kernel<128>,
                         cudaFuncAttributeMaxDynamicSharedMemorySize,
                         GEMM_SMEM_BN(128));

    // fused weight conversion prepass (fp32 -> fp16)
    {
        int n1 = (D_MODEL * D_PROJ) / 4;
        int n2 = (D_INNER * D_MODEL) / 4;
        f32h2_kernel<<<(n1 + n2 + 255) / 256, 256>>>(
            in_proj_w, (__half*)p_w1h, n1, out_proj_w, (__half*)p_w2h, n2);
    }

    rmsnorm_kernel<<<S_LEN, 256>>>(hidden, norm_w);

    // in_proj: C = xn @ W1   [2048 x 5152]
    gemm_h_kernel<128><<<dim3((D_PROJ + 127) / 128, S_LEN / GBM, 1), 256,
                         GEMM_SMEM_BN(128)>>>(
        (const __half*)p_xnh, (const __half*)p_w1h, nullptr, (float*)p_proj,
        S_LEN, D_PROJ, D_MODEL, D_MODEL);

    conv_dt_kernel<<<dim3(13, S_LEN / 4), 256>>>(conv_w, conv_b, dt_bias, A_log);

    scan_kernel<<<dim3(H_HEADS, 8), 128>>>();

    gate_kernel<<<dim3(G_GRP, S_LEN), 256>>>(Dv, gate_norm_w);

    // out_proj split-K=2: partials into g_proj (dead after gate)
    float* part = (float*)p_proj;   // p0 = part, p1 = part + S_LEN*D_MODEL
    gemm_h_kernel<128><<<dim3(D_MODEL / 128, S_LEN / GBM, 2), 256,
                         GEMM_SMEM_BN(128)>>>(
        (const __half*)p_gh, (const __half*)p_w2h, nullptr, part,
        S_LEN, D_MODEL, D_INNER / 2, D_INNER);

    addk_kernel<<<(S_LEN * D_MODEL / 4) / 256, 256>>>(
        part, part + (size_t)S_LEN * D_MODEL, hidden, out);
}